// round 1
// baseline (speedup 1.0000x reference)
#include <cuda_runtime.h>

#define NN 100000
#define HH 128
#define NE 1600000
#define NLAYERS 3

#define NT 64      // nodes per GEMM block
#define KC 64      // K chunk
#define AS_STRIDE (KC + 4)

// ---------------- scratch (device globals: no allocations allowed) ----------
__device__ int   g_cnt[NN];
__device__ int   g_rowptr[NN + 1];
__device__ int   g_cursor[NN];
__device__ int   g_csr[NE];
__device__ float g_invdeg[NN];
__device__ float g_agg[(size_t)NN * HH];
__device__ float g_xs[NLAYERS][(size_t)NN * HH];
__device__ float g_Wc[NLAYERS][256 * 128];   // combined [k][h]: k<128 -> Wl[h][k], else Wr[h][k-128]
__device__ float g_jkWT[512 * 128];          // jkWT[k][h] = jkW[h][k]

// ---------------- small setup kernels --------------------------------------
__global__ void zero_k() {
    int i = blockIdx.x * blockDim.x + threadIdx.x;
    if (i < NN) { g_cnt[i] = 0; g_cursor[i] = 0; }
}

__global__ void prep_k(const float* __restrict__ Wl, const float* __restrict__ Wr,
                       const float* __restrict__ jkW) {
    int i = blockIdx.x * blockDim.x + threadIdx.x;
    const int totW = NLAYERS * 256 * 128;
    if (i < totW) {
        int l = i >> 15;          // 32768 per layer
        int rem = i & 32767;
        int k = rem >> 7, h = rem & 127;
        float v = (k < 128) ? Wl[l * 16384 + h * 128 + k]
                            : Wr[l * 16384 + h * 128 + (k - 128)];
        g_Wc[l][k * 128 + h] = v;
    } else {
        int j = i - totW;
        if (j < 512 * 128) {
            int k = j >> 7, h = j & 127;
            g_jkWT[j] = jkW[h * 512 + k];
        }
    }
}

__global__ void count_k(const int* __restrict__ dst) {
    int i = blockIdx.x * blockDim.x + threadIdx.x;
    if (i < NE) atomicAdd(&g_cnt[dst[i]], 1);
}

// single-block chunked exclusive scan of counts -> row_ptr; also inv_deg
__global__ void scan_k() {
    __shared__ int sh[1024];
    __shared__ int carry_s;
    if (threadIdx.x == 0) carry_s = 0;
    __syncthreads();
    for (int base = 0; base < NN; base += 1024) {
        int i = base + (int)threadIdx.x;
        int v = (i < NN) ? g_cnt[i] : 0;
        sh[threadIdx.x] = v;
        __syncthreads();
        for (int off = 1; off < 1024; off <<= 1) {
            int t = (threadIdx.x >= (unsigned)off) ? sh[threadIdx.x - off] : 0;
            __syncthreads();
            sh[threadIdx.x] += t;
            __syncthreads();
        }
        int excl = sh[threadIdx.x] - v + carry_s;
        if (i < NN) {
            g_rowptr[i] = excl;
            g_invdeg[i] = 1.0f / fmaxf((float)v, 1.0f);
        }
        __syncthreads();
        if (threadIdx.x == 0) carry_s += sh[1023];
        __syncthreads();
    }
    if (threadIdx.x == 0) g_rowptr[NN] = carry_s;
}

__global__ void fill_k(const int* __restrict__ src, const int* __restrict__ dst) {
    int i = blockIdx.x * blockDim.x + threadIdx.x;
    if (i < NE) {
        int d = dst[i];
        int pos = g_rowptr[d] + atomicAdd(&g_cursor[d], 1);
        g_csr[pos] = src[i];
    }
}

// ---------------- aggregation: one warp per node, float4 per lane ----------
__global__ void agg_k(const float* __restrict__ emb, int layer) {
    const float* __restrict__ x = (layer == 0) ? emb : g_xs[layer - 1];
    int warp = (blockIdx.x * blockDim.x + threadIdx.x) >> 5;
    int lane = threadIdx.x & 31;
    if (warp >= NN) return;
    int beg = g_rowptr[warp], end = g_rowptr[warp + 1];
    const float* xb = x + lane * 4;
    float4 acc = make_float4(0.f, 0.f, 0.f, 0.f);
    int j = beg;
    for (; j + 1 < end; j += 2) {
        int s0 = g_csr[j], s1 = g_csr[j + 1];
        float4 v0 = *(const float4*)(xb + (size_t)s0 * HH);
        float4 v1 = *(const float4*)(xb + (size_t)s1 * HH);
        acc.x += v0.x + v1.x; acc.y += v0.y + v1.y;
        acc.z += v0.z + v1.z; acc.w += v0.w + v1.w;
    }
    if (j < end) {
        int s0 = g_csr[j];
        float4 v0 = *(const float4*)(xb + (size_t)s0 * HH);
        acc.x += v0.x; acc.y += v0.y; acc.z += v0.z; acc.w += v0.w;
    }
    float inv = g_invdeg[warp];
    acc.x *= inv; acc.y *= inv; acc.z *= inv; acc.w *= inv;
    *(float4*)(g_agg + (size_t)warp * HH + lane * 4) = acc;
}

// ---------------- fused GEMM (K=256) + bias + LN + ReLU + residual ---------
// C[64,128] = [agg | xin] @ Wc ; per-thread 4x8 register tile.
__global__ __launch_bounds__(256) void gemm_ln_k(
    const float* __restrict__ emb, int layer,
    const float* __restrict__ bl_all,
    const float* __restrict__ gamma_all, const float* __restrict__ beta_all) {
    extern __shared__ float smem_dyn[];
    float (*As)[AS_STRIDE] = (float(*)[AS_STRIDE])smem_dyn;
    float (*Bs)[128]       = (float(*)[128])(smem_dyn + NT * AS_STRIDE);

    const float* __restrict__ xin = (layer == 0) ? emb : g_xs[layer - 1];
    float* __restrict__ xout = g_xs[layer];
    const float* __restrict__ Wc = g_Wc[layer];
    const float* __restrict__ bias  = bl_all + layer * 128;
    const float* __restrict__ gamma = gamma_all + layer * 128;
    const float* __restrict__ beta  = beta_all + layer * 128;

    int tid = threadIdx.x;
    int r = tid >> 4;        // 0..15 (row group)
    int cc = tid & 15;       // 0..15 (col group)
    int c8 = cc * 8;
    int n0 = blockIdx.x * NT;
    int ln = tid >> 2, q = tid & 3;   // A loader mapping

    float acc[4][8];
    #pragma unroll
    for (int i = 0; i < 4; i++)
        #pragma unroll
        for (int jj = 0; jj < 8; jj++) acc[i][jj] = 0.f;

    #pragma unroll
    for (int ch = 0; ch < 4; ch++) {
        const int k0 = ch * KC;
        // load A chunk [64][64]
        {
            int n = n0 + ln;
            const float* srcp = (k0 < HH) ? (g_agg + (size_t)n * HH + k0)
                                          : (xin + (size_t)n * HH + (k0 - HH));
            #pragma unroll
            for (int v = 0; v < 4; v++) {
                int kk = q * 16 + v * 4;
                float4 val = make_float4(0.f, 0.f, 0.f, 0.f);
                if (n < NN) val = *(const float4*)(srcp + kk);
                *(float4*)&As[ln][kk] = val;
            }
        }
        // load B chunk [64][128]
        #pragma unroll
        for (int v = 0; v < 8; v++) {
            int idx = (v * 256 + tid) * 4;
            int kk = idx >> 7, h = idx & 127;
            *(float4*)&Bs[kk][h] = *(const float4*)(Wc + (size_t)(k0 + kk) * 128 + h);
        }
        __syncthreads();
        #pragma unroll 16
        for (int kk = 0; kk < KC; kk++) {
            float a[4];
            #pragma unroll
            for (int i = 0; i < 4; i++) a[i] = As[r * 4 + i][kk];
            float4 b0 = *(const float4*)&Bs[kk][c8];
            float4 b1 = *(const float4*)&Bs[kk][c8 + 4];
            float b[8] = {b0.x, b0.y, b0.z, b0.w, b1.x, b1.y, b1.z, b1.w};
            #pragma unroll
            for (int i = 0; i < 4; i++)
                #pragma unroll
                for (int jj = 0; jj < 8; jj++)
                    acc[i][jj] = fmaf(a[i], b[jj], acc[i][jj]);
        }
        __syncthreads();
    }

    // epilogue: bias -> LN (shfl over 16-lane row group) -> ReLU -> residual
    float bb[8], gg[8], be[8];
    {
        float4 t0 = *(const float4*)(bias + c8),  t1 = *(const float4*)(bias + c8 + 4);
        float4 g0 = *(const float4*)(gamma + c8), g1 = *(const float4*)(gamma + c8 + 4);
        float4 e0 = *(const float4*)(beta + c8),  e1 = *(const float4*)(beta + c8 + 4);
        bb[0]=t0.x;bb[1]=t0.y;bb[2]=t0.z;bb[3]=t0.w;bb[4]=t1.x;bb[5]=t1.y;bb[6]=t1.z;bb[7]=t1.w;
        gg[0]=g0.x;gg[1]=g0.y;gg[2]=g0.z;gg[3]=g0.w;gg[4]=g1.x;gg[5]=g1.y;gg[6]=g1.z;gg[7]=g1.w;
        be[0]=e0.x;be[1]=e0.y;be[2]=e0.z;be[3]=e0.w;be[4]=e1.x;be[5]=e1.y;be[6]=e1.z;be[7]=e1.w;
    }
    const float inv128 = 1.0f / 128.0f;
    #pragma unroll
    for (int i = 0; i < 4; i++) {
        int n = n0 + r * 4 + i;
        float v[8], s = 0.f, s2 = 0.f;
        #pragma unroll
        for (int jj = 0; jj < 8; jj++) {
            v[jj] = acc[i][jj] + bb[jj];
            s += v[jj]; s2 += v[jj] * v[jj];
        }
        #pragma unroll
        for (int o = 1; o < 16; o <<= 1) {
            s  += __shfl_xor_sync(0xffffffffu, s,  o);
            s2 += __shfl_xor_sync(0xffffffffu, s2, o);
        }
        float mu = s * inv128;
        float var = s2 * inv128 - mu * mu;
        float rs = rsqrtf(var + 1e-5f);
        if (n < NN) {
            float o[8];
            #pragma unroll
            for (int jj = 0; jj < 8; jj++) {
                float y = (v[jj] - mu) * rs * gg[jj] + be[jj];
                o[jj] = fmaxf(y, 0.f);
            }
            if (layer > 0) {
                float4 r0 = *(const float4*)(xin + (size_t)n * HH + c8);
                float4 r1 = *(const float4*)(xin + (size_t)n * HH + c8 + 4);
                o[0]+=r0.x;o[1]+=r0.y;o[2]+=r0.z;o[3]+=r0.w;
                o[4]+=r1.x;o[5]+=r1.y;o[6]+=r1.z;o[7]+=r1.w;
            }
            float4 w0 = make_float4(o[0],o[1],o[2],o[3]);
            float4 w1 = make_float4(o[4],o[5],o[6],o[7]);
            *(float4*)(xout + (size_t)n * HH + c8)     = w0;
            *(float4*)(xout + (size_t)n * HH + c8 + 4) = w1;
        }
    }
}

// ---------------- JK head: [N,512] @ jkWT -> out, + jkb --------------------
__global__ __launch_bounds__(256) void jk_k(
    const float* __restrict__ emb, const float* __restrict__ jkb,
    float* __restrict__ out) {
    extern __shared__ float smem_dyn[];
    float (*As)[AS_STRIDE] = (float(*)[AS_STRIDE])smem_dyn;
    float (*Bs)[128]       = (float(*)[128])(smem_dyn + NT * AS_STRIDE);

    const float* slices[4] = {emb, g_xs[0], g_xs[1], g_xs[2]};

    int tid = threadIdx.x;
    int r = tid >> 4, cc = tid & 15, c8 = cc * 8;
    int n0 = blockIdx.x * NT;
    int ln = tid >> 2, q = tid & 3;

    float acc[4][8];
    #pragma unroll
    for (int i = 0; i < 4; i++)
        #pragma unroll
        for (int jj = 0; jj < 8; jj++) acc[i][jj] = 0.f;

    for (int ch = 0; ch < 8; ch++) {
        const int k0 = ch * KC;
        const float* base = slices[ch >> 1] ;
        const int off = (ch & 1) * 64;
        {
            int n = n0 + ln;
            const float* srcp = base + (size_t)n * HH + off;
            #pragma unroll
            for (int v = 0; v < 4; v++) {
                int kk = q * 16 + v * 4;
                float4 val = make_float4(0.f, 0.f, 0.f, 0.f);
                if (n < NN) val = *(const float4*)(srcp + kk);
                *(float4*)&As[ln][kk] = val;
            }
        }
        #pragma unroll
        for (int v = 0; v < 8; v++) {
            int idx = (v * 256 + tid) * 4;
            int kk = idx >> 7, h = idx & 127;
            *(float4*)&Bs[kk][h] = *(const float4*)(g_jkWT + (size_t)(k0 + kk) * 128 + h);
        }
        __syncthreads();
        #pragma unroll 16
        for (int kk = 0; kk < KC; kk++) {
            float a[4];
            #pragma unroll
            for (int i = 0; i < 4; i++) a[i] = As[r * 4 + i][kk];
            float4 b0 = *(const float4*)&Bs[kk][c8];
            float4 b1 = *(const float4*)&Bs[kk][c8 + 4];
            float b[8] = {b0.x, b0.y, b0.z, b0.w, b1.x, b1.y, b1.z, b1.w};
            #pragma unroll
            for (int i = 0; i < 4; i++)
                #pragma unroll
                for (int jj = 0; jj < 8; jj++)
                    acc[i][jj] = fmaf(a[i], b[jj], acc[i][jj]);
        }
        __syncthreads();
    }

    float bb[8];
    {
        float4 t0 = *(const float4*)(jkb + c8), t1 = *(const float4*)(jkb + c8 + 4);
        bb[0]=t0.x;bb[1]=t0.y;bb[2]=t0.z;bb[3]=t0.w;bb[4]=t1.x;bb[5]=t1.y;bb[6]=t1.z;bb[7]=t1.w;
    }
    #pragma unroll
    for (int i = 0; i < 4; i++) {
        int n = n0 + r * 4 + i;
        if (n < NN) {
            float4 w0 = make_float4(acc[i][0]+bb[0], acc[i][1]+bb[1], acc[i][2]+bb[2], acc[i][3]+bb[3]);
            float4 w1 = make_float4(acc[i][4]+bb[4], acc[i][5]+bb[5], acc[i][6]+bb[6], acc[i][7]+bb[7]);
            *(float4*)(out + (size_t)n * HH + c8)     = w0;
            *(float4*)(out + (size_t)n * HH + c8 + 4) = w1;
        }
    }
}

// ---------------- launch ----------------------------------------------------
extern "C" void kernel_launch(void* const* d_in, const int* in_sizes, int n_in,
                              void* d_out, int out_size) {
    const float* emb   = (const float*)d_in[0];
    const float* Wl    = (const float*)d_in[1];
    const float* bl    = (const float*)d_in[2];
    const float* Wr    = (const float*)d_in[3];
    const float* gamma = (const float*)d_in[4];
    const float* beta  = (const float*)d_in[5];
    const float* jkW   = (const float*)d_in[6];
    const float* jkb   = (const float*)d_in[7];
    const int*   eidx  = (const int*)d_in[8];
    const int* src = eidx;
    const int* dst = eidx + NE;
    float* out = (float*)d_out;

    const int SMEMSZ = (NT * AS_STRIDE + KC * 128) * (int)sizeof(float);  // 50176 B
    cudaFuncSetAttribute(gemm_ln_k, cudaFuncAttributeMaxDynamicSharedMemorySize, SMEMSZ);
    cudaFuncSetAttribute(jk_k,      cudaFuncAttributeMaxDynamicSharedMemorySize, SMEMSZ);

    zero_k<<<(NN + 255) / 256, 256>>>();
    prep_k<<<(NLAYERS * 256 * 128 + 512 * 128 + 255) / 256, 256>>>(Wl, Wr, jkW);
    count_k<<<(NE + 255) / 256, 256>>>(dst);
    scan_k<<<1, 1024>>>();
    fill_k<<<(NE + 255) / 256, 256>>>(src, dst);

    for (int l = 0; l < NLAYERS; l++) {
        agg_k<<<(NN + 7) / 8, 256>>>(emb, l);
        gemm_ln_k<<<(NN + NT - 1) / NT, 256, SMEMSZ>>>(emb, l, bl, gamma, beta);
    }
    jk_k<<<(NN + NT - 1) / NT, 256, SMEMSZ>>>(emb, jkb, out);
}

// round 3
// speedup vs baseline: 2.1711x; 2.1711x over previous
#include <cuda_runtime.h>
#include <cuda_bf16.h>

#define NN 100000
#define HH 128
#define NE 1600000
#define NL 3
#define NB 98   // scan blocks = ceil(NN/1024)

// ---------------- scratch (device globals) ----------------------------------
__device__ int   g_cnt[NN];
__device__ int   g_rowptr[NN + 1];
__device__ int   g_cursor[NN];
__device__ int   g_csr[NE];
__device__ int   g_blksum[128];
__device__ float g_invdeg[NN];
__device__ float g_agg[(size_t)NN * HH];
__device__ float g_xs[NL][(size_t)NN * HH];
// weights pre-split to bf16 hi/lo, layout [h][k] (k contiguous) for mma col-B
__device__ __nv_bfloat16 g_Wb[NL][2][128 * 256];
__device__ __nv_bfloat16 g_jkWb[2][128 * 512];

// ---------------- helpers ----------------------------------------------------
__device__ __forceinline__ void cvt_hilo(float x, float y, unsigned& hi, unsigned& lo) {
    __nv_bfloat162 h = __floats2bfloat162_rn(x, y);
    float hx = __bfloat162float(h.x), hy = __bfloat162float(h.y);
    __nv_bfloat162 l = __floats2bfloat162_rn(x - hx, y - hy);
    hi = *reinterpret_cast<unsigned*>(&h);
    lo = *reinterpret_cast<unsigned*>(&l);
}

#define MMA16816(d, a, b) asm volatile( \
    "mma.sync.aligned.m16n8k16.row.col.f32.bf16.bf16.f32 " \
    "{%0,%1,%2,%3}, {%4,%5,%6,%7}, {%8,%9}, {%0,%1,%2,%3};" \
    : "+f"((d)[0]), "+f"((d)[1]), "+f"((d)[2]), "+f"((d)[3]) \
    : "r"((a)[0]), "r"((a)[1]), "r"((a)[2]), "r"((a)[3]), \
      "r"((b)[0]), "r"((b)[1]))

// ---------------- setup kernels ---------------------------------------------
__global__ void zero_k() {
    int i = blockIdx.x * blockDim.x + threadIdx.x;
    if (i < NN) { g_cnt[i] = 0; g_cursor[i] = 0; }
}

__global__ void prep_k(const float* __restrict__ Wl, const float* __restrict__ Wr,
                       const float* __restrict__ jkW) {
    int i = blockIdx.x * blockDim.x + threadIdx.x;
    const int totW = NL * 128 * 256;
    float w; int dstl = -1, dsti = 0;
    if (i < totW) {
        int l = i >> 15;             // 128*256 = 32768 per layer
        int rem = i & 32767;
        int h = rem >> 8, k = rem & 255;
        w = (k < 128) ? Wl[l * 16384 + h * 128 + k]
                      : Wr[l * 16384 + h * 128 + (k - 128)];
        dstl = l; dsti = rem;
    } else {
        int j = i - totW;
        if (j >= 128 * 512) return;
        w = jkW[j];                   // jkW is [h][k] already, k contiguous
        dsti = j;
    }
    __nv_bfloat16 hi = __float2bfloat16(w);
    __nv_bfloat16 lo = __float2bfloat16(w - __bfloat162float(hi));
    if (dstl >= 0) { g_Wb[dstl][0][dsti] = hi; g_Wb[dstl][1][dsti] = lo; }
    else           { g_jkWb[0][dsti] = hi;     g_jkWb[1][dsti] = lo; }
}

__global__ void count_k(const int* __restrict__ dst) {
    int i = blockIdx.x * blockDim.x + threadIdx.x;
    if (i < NE) atomicAdd(&g_cnt[dst[i]], 1);
}

// parallel scan phase 1: per-block exclusive scan + block totals
__global__ void scan1_k() {
    __shared__ int sh[1024];
    int i = blockIdx.x * 1024 + threadIdx.x;
    int v = (i < NN) ? g_cnt[i] : 0;
    sh[threadIdx.x] = v;
    __syncthreads();
    #pragma unroll
    for (int off = 1; off < 1024; off <<= 1) {
        int t = (threadIdx.x >= (unsigned)off) ? sh[threadIdx.x - off] : 0;
        __syncthreads();
        sh[threadIdx.x] += t;
        __syncthreads();
    }
    if (i < NN) {
        g_rowptr[i] = sh[threadIdx.x] - v;
        g_invdeg[i] = 1.0f / fmaxf((float)v, 1.0f);
    }
    if (threadIdx.x == 1023) g_blksum[blockIdx.x] = sh[1023];
}

// phase 2: scan the 98 block totals (single small block)
__global__ void scan2_k() {
    __shared__ int sh[128];
    int t = threadIdx.x;
    int v = (t < NB) ? g_blksum[t] : 0;
    sh[t] = v;
    __syncthreads();
    #pragma unroll
    for (int off = 1; off < 128; off <<= 1) {
        int u = (t >= off) ? sh[t - off] : 0;
        __syncthreads();
        sh[t] += u;
        __syncthreads();
    }
    if (t < NB) g_blksum[t] = sh[t] - v;   // exclusive
    if (t == 127) g_rowptr[NN] = sh[127];
}

// phase 3: add block offsets
__global__ void scan3_k() {
    int i = blockIdx.x * 1024 + threadIdx.x;
    if (i < NN) g_rowptr[i] += g_blksum[blockIdx.x];
}

__global__ void fill_k(const int* __restrict__ src, const int* __restrict__ dst) {
    int i = blockIdx.x * blockDim.x + threadIdx.x;
    if (i < NE) {
        int d = dst[i];
        int pos = g_rowptr[d] + atomicAdd(&g_cursor[d], 1);
        g_csr[pos] = src[i];
    }
}

// ---------------- aggregation: one warp per node, float4 per lane ----------
__global__ void agg_k(const float* __restrict__ emb, int layer) {
    const float* __restrict__ x = (layer == 0) ? emb : g_xs[layer - 1];
    int warp = (blockIdx.x * blockDim.x + threadIdx.x) >> 5;
    int lane = threadIdx.x & 31;
    if (warp >= NN) return;
    int beg = g_rowptr[warp], end = g_rowptr[warp + 1];
    const float* xb = x + lane * 4;
    float4 acc = make_float4(0.f, 0.f, 0.f, 0.f);
    int j = beg;
    for (; j + 1 < end; j += 2) {
        int s0 = g_csr[j], s1 = g_csr[j + 1];
        float4 v0 = *(const float4*)(xb + (size_t)s0 * HH);
        float4 v1 = *(const float4*)(xb + (size_t)s1 * HH);
        acc.x += v0.x + v1.x; acc.y += v0.y + v1.y;
        acc.z += v0.z + v1.z; acc.w += v0.w + v1.w;
    }
    if (j < end) {
        int s0 = g_csr[j];
        float4 v0 = *(const float4*)(xb + (size_t)s0 * HH);
        acc.x += v0.x; acc.y += v0.y; acc.z += v0.z; acc.w += v0.w;
    }
    float inv = g_invdeg[warp];
    acc.x *= inv; acc.y *= inv; acc.z *= inv; acc.w *= inv;
    *(float4*)(g_agg + (size_t)warp * HH + lane * 4) = acc;
}

// ---------------- tensor-core GEMM (bf16 3-term split) + LN fusion ---------
// Block: 128 rows x 128 cols, K = 256 ([agg | xin]), 8 warps (4m x 2n).
__global__ __launch_bounds__(256) void gemm_ln_k(
    const float* __restrict__ emb, int layer,
    const float* __restrict__ bl_all,
    const float* __restrict__ gamma_all, const float* __restrict__ beta_all) {
    __shared__ unsigned Ah[128][17], Al[128][17], Bh[128][17], Bl[128][17];
    __shared__ float red_s[2][128], red_q[2][128];

    const float* __restrict__ xin = (layer == 0) ? emb : g_xs[layer - 1];
    float* __restrict__ xout = g_xs[layer];
    const __nv_bfloat16* __restrict__ WH = g_Wb[layer][0];
    const __nv_bfloat16* __restrict__ WL = g_Wb[layer][1];
    const float* __restrict__ bias  = bl_all + layer * 128;
    const float* __restrict__ gamma = gamma_all + layer * 128;
    const float* __restrict__ beta  = beta_all + layer * 128;

    int tid = threadIdx.x, wid = tid >> 5, lane = tid & 31;
    int wm = wid & 3, wn = wid >> 2;
    int n0 = blockIdx.x * 128;
    int arow = tid >> 1, half = tid & 1;

    float acc[2][8][4];
    #pragma unroll
    for (int mt = 0; mt < 2; mt++)
        #pragma unroll
        for (int nt = 0; nt < 8; nt++)
            #pragma unroll
            for (int c = 0; c < 4; c++) acc[mt][nt][c] = 0.f;

    #pragma unroll 1
    for (int ch = 0; ch < 8; ch++) {
        const int k0 = ch * 32;
        // A: 128 rows x 32 cols fp32 -> bf16 hi/lo planes
        {
            int n = n0 + arow;
            const float* srcp = (k0 < HH) ? (g_agg + (size_t)n * HH + k0)
                                          : (xin + (size_t)n * HH + (k0 - HH));
            #pragma unroll
            for (int t = 0; t < 4; t++) {
                float4 v = make_float4(0.f, 0.f, 0.f, 0.f);
                if (n < NN) v = *(const float4*)(srcp + half * 16 + t * 4);
                unsigned h0, l0, h1, l1;
                cvt_hilo(v.x, v.y, h0, l0);
                cvt_hilo(v.z, v.w, h1, l1);
                int j = half * 8 + t * 2;
                Ah[arow][j] = h0; Ah[arow][j + 1] = h1;
                Al[arow][j] = l0; Al[arow][j + 1] = l1;
            }
        }
        // B: 128 cols(h) x 32 k from prepped planes ([h][256] bf16)
        {
            const unsigned* bh = (const unsigned*)WH + arow * 128 + (k0 >> 1) + half * 8;
            const unsigned* blp = (const unsigned*)WL + arow * 128 + (k0 >> 1) + half * 8;
            uint4 vh0 = *(const uint4*)bh,       vh1 = *(const uint4*)(bh + 4);
            uint4 vl0 = *(const uint4*)blp,      vl1 = *(const uint4*)(blp + 4);
            int j = half * 8;
            Bh[arow][j+0]=vh0.x; Bh[arow][j+1]=vh0.y; Bh[arow][j+2]=vh0.z; Bh[arow][j+3]=vh0.w;
            Bh[arow][j+4]=vh1.x; Bh[arow][j+5]=vh1.y; Bh[arow][j+6]=vh1.z; Bh[arow][j+7]=vh1.w;
            Bl[arow][j+0]=vl0.x; Bl[arow][j+1]=vl0.y; Bl[arow][j+2]=vl0.z; Bl[arow][j+3]=vl0.w;
            Bl[arow][j+4]=vl1.x; Bl[arow][j+5]=vl1.y; Bl[arow][j+6]=vl1.z; Bl[arow][j+7]=vl1.w;
        }
        __syncthreads();
        #pragma unroll
        for (int s = 0; s < 2; s++) {
            int kc = s * 8 + (lane & 3);
            unsigned bH[8][2], bL[8][2];
            #pragma unroll
            for (int nt = 0; nt < 8; nt++) {
                int n = wn * 64 + nt * 8 + (lane >> 2);
                bH[nt][0] = Bh[n][kc]; bH[nt][1] = Bh[n][kc + 4];
                bL[nt][0] = Bl[n][kc]; bL[nt][1] = Bl[n][kc + 4];
            }
            #pragma unroll
            for (int mt = 0; mt < 2; mt++) {
                int r = wm * 32 + mt * 16 + (lane >> 2);
                unsigned aH[4], aL[4];
                aH[0] = Ah[r][kc]; aH[1] = Ah[r + 8][kc];
                aH[2] = Ah[r][kc + 4]; aH[3] = Ah[r + 8][kc + 4];
                aL[0] = Al[r][kc]; aL[1] = Al[r + 8][kc];
                aL[2] = Al[r][kc + 4]; aL[3] = Al[r + 8][kc + 4];
                #pragma unroll
                for (int nt = 0; nt < 8; nt++) {
                    MMA16816(acc[mt][nt], aH, bH[nt]);
                    MMA16816(acc[mt][nt], aH, bL[nt]);
                    MMA16816(acc[mt][nt], aL, bH[nt]);
                }
            }
        }
        __syncthreads();
    }

    // ---- epilogue: bias -> LN -> ReLU -> residual ----
    int cbase = wn * 64 + (lane & 3) * 2;
    float bb[8][2], gg[8][2], be[8][2];
    #pragma unroll
    for (int nt = 0; nt < 8; nt++) {
        int col = cbase + nt * 8;
        bb[nt][0] = bias[col];  bb[nt][1] = bias[col + 1];
        gg[nt][0] = gamma[col]; gg[nt][1] = gamma[col + 1];
        be[nt][0] = beta[col];  be[nt][1] = beta[col + 1];
    }
    #pragma unroll
    for (int mt = 0; mt < 2; mt++)
        #pragma unroll
        for (int rr = 0; rr < 2; rr++) {
            float s = 0.f, q2 = 0.f;
            #pragma unroll
            for (int nt = 0; nt < 8; nt++)
                #pragma unroll
                for (int q = 0; q < 2; q++) {
                    float v = acc[mt][nt][rr * 2 + q] + bb[nt][q];
                    acc[mt][nt][rr * 2 + q] = v;
                    s += v; q2 += v * v;
                }
            s  += __shfl_xor_sync(0xffffffffu, s, 1);
            s  += __shfl_xor_sync(0xffffffffu, s, 2);
            q2 += __shfl_xor_sync(0xffffffffu, q2, 1);
            q2 += __shfl_xor_sync(0xffffffffu, q2, 2);
            if ((lane & 3) == 0) {
                int rb = wm * 32 + mt * 16 + rr * 8 + (lane >> 2);
                red_s[wn][rb] = s; red_q[wn][rb] = q2;
            }
        }
    __syncthreads();
    const float inv128 = 1.0f / 128.0f;
    #pragma unroll
    for (int mt = 0; mt < 2; mt++)
        #pragma unroll
        for (int rr = 0; rr < 2; rr++) {
            int rb = wm * 32 + mt * 16 + rr * 8 + (lane >> 2);
            int n = n0 + rb;
            float S = red_s[0][rb] + red_s[1][rb];
            float Q = red_q[0][rb] + red_q[1][rb];
            float mu = S * inv128;
            float var = Q * inv128 - mu * mu;
            float rs = rsqrtf(var + 1e-5f);
            if (n < NN) {
                #pragma unroll
                for (int nt = 0; nt < 8; nt++) {
                    int col = cbase + nt * 8;
                    float y0 = (acc[mt][nt][rr*2+0] - mu) * rs * gg[nt][0] + be[nt][0];
                    float y1 = (acc[mt][nt][rr*2+1] - mu) * rs * gg[nt][1] + be[nt][1];
                    y0 = fmaxf(y0, 0.f); y1 = fmaxf(y1, 0.f);
                    if (layer > 0) {
                        float2 rv = *(const float2*)(xin + (size_t)n * HH + col);
                        y0 += rv.x; y1 += rv.y;
                    }
                    *(float2*)(xout + (size_t)n * HH + col) = make_float2(y0, y1);
                }
            }
        }
}

// ---------------- JK head: K=512 tensor-core GEMM + bias -------------------
__global__ __launch_bounds__(256) void jk_k(
    const float* __restrict__ emb, const float* __restrict__ jkb,
    float* __restrict__ out) {
    __shared__ unsigned Ah[128][17], Al[128][17], Bh[128][17], Bl[128][17];

    int tid = threadIdx.x, wid = tid >> 5, lane = tid & 31;
    int wm = wid & 3, wn = wid >> 2;
    int n0 = blockIdx.x * 128;
    int arow = tid >> 1, half = tid & 1;

    float acc[2][8][4];
    #pragma unroll
    for (int mt = 0; mt < 2; mt++)
        #pragma unroll
        for (int nt = 0; nt < 8; nt++)
            #pragma unroll
            for (int c = 0; c < 4; c++) acc[mt][nt][c] = 0.f;

    #pragma unroll 1
    for (int ch = 0; ch < 16; ch++) {
        const int k0 = ch * 32;
        const float* base = (ch < 4) ? emb : g_xs[(ch >> 2) - 1];
        const int off = (ch & 3) * 32;
        {
            int n = n0 + arow;
            const float* srcp = base + (size_t)n * HH + off;
            #pragma unroll
            for (int t = 0; t < 4; t++) {
                float4 v = make_float4(0.f, 0.f, 0.f, 0.f);
                if (n < NN) v = *(const float4*)(srcp + half * 16 + t * 4);
                unsigned h0, l0, h1, l1;
                cvt_hilo(v.x, v.y, h0, l0);
                cvt_hilo(v.z, v.w, h1, l1);
                int j = half * 8 + t * 2;
                Ah[arow][j] = h0; Ah[arow][j + 1] = h1;
                Al[arow][j] = l0; Al[arow][j + 1] = l1;
            }
        }
        {
            const unsigned* bh = (const unsigned*)g_jkWb[0] + arow * 256 + (k0 >> 1) + half * 8;
            const unsigned* blp = (const unsigned*)g_jkWb[1] + arow * 256 + (k0 >> 1) + half * 8;
            uint4 vh0 = *(const uint4*)bh,  vh1 = *(const uint4*)(bh + 4);
            uint4 vl0 = *(const uint4*)blp, vl1 = *(const uint4*)(blp + 4);
            int j = half * 8;
            Bh[arow][j+0]=vh0.x; Bh[arow][j+1]=vh0.y; Bh[arow][j+2]=vh0.z; Bh[arow][j+3]=vh0.w;
            Bh[arow][j+4]=vh1.x; Bh[arow][j+5]=vh1.y; Bh[arow][j+6]=vh1.z; Bh[arow][j+7]=vh1.w;
            Bl[arow][j+0]=vl0.x; Bl[arow][j+1]=vl0.y; Bl[arow][j+2]=vl0.z; Bl[arow][j+3]=vl0.w;
            Bl[arow][j+4]=vl1.x; Bl[arow][j+5]=vl1.y; Bl[arow][j+6]=vl1.z; Bl[arow][j+7]=vl1.w;
        }
        __syncthreads();
        #pragma unroll
        for (int s = 0; s < 2; s++) {
            int kc = s * 8 + (lane & 3);
            unsigned bH[8][2], bL[8][2];
            #pragma unroll
            for (int nt = 0; nt < 8; nt++) {
                int n = wn * 64 + nt * 8 + (lane >> 2);
                bH[nt][0] = Bh[n][kc]; bH[nt][1] = Bh[n][kc + 4];
                bL[nt][0] = Bl[n][kc]; bL[nt][1] = Bl[n][kc + 4];
            }
            #pragma unroll
            for (int mt = 0; mt < 2; mt++) {
                int r = wm * 32 + mt * 16 + (lane >> 2);
                unsigned aH[4], aL[4];
                aH[0] = Ah[r][kc]; aH[1] = Ah[r + 8][kc];
                aH[2] = Ah[r][kc + 4]; aH[3] = Ah[r + 8][kc + 4];
                aL[0] = Al[r][kc]; aL[1] = Al[r + 8][kc];
                aL[2] = Al[r][kc + 4]; aL[3] = Al[r + 8][kc + 4];
                #pragma unroll
                for (int nt = 0; nt < 8; nt++) {
                    MMA16816(acc[mt][nt], aH, bH[nt]);
                    MMA16816(acc[mt][nt], aH, bL[nt]);
                    MMA16816(acc[mt][nt], aL, bH[nt]);
                }
            }
        }
        __syncthreads();
    }

    int cbase = wn * 64 + (lane & 3) * 2;
    float bb[8][2];
    #pragma unroll
    for (int nt = 0; nt < 8; nt++) {
        int col = cbase + nt * 8;
        bb[nt][0] = jkb[col]; bb[nt][1] = jkb[col + 1];
    }
    #pragma unroll
    for (int mt = 0; mt < 2; mt++)
        #pragma unroll
        for (int rr = 0; rr < 2; rr++) {
            int rb = wm * 32 + mt * 16 + rr * 8 + (lane >> 2);
            int n = n0 + rb;
            if (n < NN) {
                #pragma unroll
                for (int nt = 0; nt < 8; nt++) {
                    int col = cbase + nt * 8;
                    *(float2*)(out + (size_t)n * HH + col) =
                        make_float2(acc[mt][nt][rr*2+0] + bb[nt][0],
                                    acc[mt][nt][rr*2+1] + bb[nt][1]);
                }
            }
        }
}

// ---------------- launch ----------------------------------------------------
extern "C" void kernel_launch(void* const* d_in, const int* in_sizes, int n_in,
                              void* d_out, int out_size) {
    const float* emb   = (const float*)d_in[0];
    const float* Wl    = (const float*)d_in[1];
    const float* bl    = (const float*)d_in[2];
    const float* Wr    = (const float*)d_in[3];
    const float* gamma = (const float*)d_in[4];
    const float* beta  = (const float*)d_in[5];
    const float* jkW   = (const float*)d_in[6];
    const float* jkb   = (const float*)d_in[7];
    const int*   eidx  = (const int*)d_in[8];
    const int* src = eidx;
    const int* dst = eidx + NE;
    float* out = (float*)d_out;

    zero_k<<<(NN + 255) / 256, 256>>>();
    prep_k<<<(NL * 128 * 256 + 128 * 512 + 255) / 256, 256>>>(Wl, Wr, jkW);
    count_k<<<(NE + 255) / 256, 256>>>(dst);
    scan1_k<<<NB, 1024>>>();
    scan2_k<<<1, 128>>>();
    scan3_k<<<NB, 1024>>>();
    fill_k<<<(NE + 255) / 256, 256>>>(src, dst);

    const int GB = (NN + 127) / 128;   // 782
    for (int l = 0; l < NL; l++) {
        agg_k<<<(NN + 7) / 8, 256>>>(emb, l);
        gemm_ln_k<<<GB, 256>>>(emb, l, bl, gamma, beta);
    }
    jk_k<<<GB, 256>>>(emb, jkb, out);
}

// round 6
// speedup vs baseline: 2.3160x; 1.0667x over previous
#include <cuda_runtime.h>
#include <cuda_bf16.h>
#include <stdint.h>

#define NN 100000
#define HH 128
#define NE 1600000
#define NL 3
#define NB 98   // scan blocks = ceil(NN/1024)

#define STRD 20              // smem row stride in 32-bit words (ldmatrix conflict-free)
#define PLANE (128 * STRD)   // one 128-row plane, in words

// ---------------- scratch (device globals) ----------------------------------
__device__ int   g_cnt[NN];
__device__ int   g_rowptr[NN + 1];
__device__ int   g_cursor[NN];
__device__ int   g_csr[NE];
__device__ int   g_state[NB];
__device__ int   g_aggv[NB];
__device__ int   g_prefv[NB];
__device__ float g_invdeg[NN];
__device__ float g_agg[(size_t)NN * HH];
__device__ float g_xs[NL][(size_t)NN * HH];
// weights pre-split to bf16 hi/lo, layout [h][k] (k contiguous)
__device__ __nv_bfloat16 g_Wb[NL][2][128 * 256];
__device__ __nv_bfloat16 g_jkWb[2][128 * 512];

// ---------------- helpers ----------------------------------------------------
__device__ __forceinline__ void cvt_hilo(float x, float y, unsigned& hi, unsigned& lo) {
    __nv_bfloat162 h = __floats2bfloat162_rn(x, y);
    float hx = __bfloat162float(h.x), hy = __bfloat162float(h.y);
    __nv_bfloat162 l = __floats2bfloat162_rn(x - hx, y - hy);
    hi = *reinterpret_cast<unsigned*>(&h);
    lo = *reinterpret_cast<unsigned*>(&l);
}

#define MMA16816(d, a, b) asm volatile( \
    "mma.sync.aligned.m16n8k16.row.col.f32.bf16.bf16.f32 " \
    "{%0,%1,%2,%3}, {%4,%5,%6,%7}, {%8,%9}, {%0,%1,%2,%3};" \
    : "+f"((d)[0]), "+f"((d)[1]), "+f"((d)[2]), "+f"((d)[3]) \
    : "r"((a)[0]), "r"((a)[1]), "r"((a)[2]), "r"((a)[3]), \
      "r"((b)[0]), "r"((b)[1]))

__device__ __forceinline__ void ldsm4(unsigned* r, uint32_t addr) {
    asm volatile("ldmatrix.sync.aligned.m8n8.x4.shared.b16 {%0,%1,%2,%3}, [%4];"
                 : "=r"(r[0]), "=r"(r[1]), "=r"(r[2]), "=r"(r[3]) : "r"(addr));
}

#define CP16(dst, src) asm volatile("cp.async.cg.shared.global [%0], [%1], 16;" :: "r"(dst), "l"(src))
#define CP_COMMIT()    asm volatile("cp.async.commit_group;")
#define CP_WAIT(n)     asm volatile("cp.async.wait_group %0;" :: "n"(n))

// ---------------- setup: zero counters/state + weight split -----------------
__global__ void init_k(const float* __restrict__ Wl, const float* __restrict__ Wr,
                       const float* __restrict__ jkW) {
    int i = blockIdx.x * blockDim.x + threadIdx.x;
    if (i < NN) { g_cnt[i] = 0; g_cursor[i] = 0; }
    if (i < NB) g_state[i] = 0;
    const int totW = NL * 128 * 256;
    float w; int dstl = -1, dsti = 0;
    if (i < totW) {
        int l = i >> 15;
        int rem = i & 32767;
        int h = rem >> 8, k = rem & 255;
        w = (k < 128) ? Wl[l * 16384 + h * 128 + k]
                      : Wr[l * 16384 + h * 128 + (k - 128)];
        dstl = l; dsti = rem;
    } else {
        int j = i - totW;
        if (j >= 128 * 512) return;
        w = jkW[j];
        dsti = j;
    }
    __nv_bfloat16 hi = __float2bfloat16(w);
    __nv_bfloat16 lo = __float2bfloat16(w - __bfloat162float(hi));
    if (dstl >= 0) { g_Wb[dstl][0][dsti] = hi; g_Wb[dstl][1][dsti] = lo; }
    else           { g_jkWb[0][dsti] = hi;     g_jkWb[1][dsti] = lo; }
}

__global__ void count_k(const int* __restrict__ dst) {
    int i = blockIdx.x * blockDim.x + threadIdx.x;
    if (i < NE) atomicAdd(&g_cnt[dst[i]], 1);
}

// single-kernel decoupled-lookback exclusive scan (98 co-resident blocks)
__global__ void scan_k() {
    __shared__ int sh[1024];
    __shared__ int s_excl;
    int bid = blockIdx.x;
    int i = bid * 1024 + (int)threadIdx.x;
    int v = (i < NN) ? g_cnt[i] : 0;
    sh[threadIdx.x] = v;
    __syncthreads();
    #pragma unroll
    for (int off = 1; off < 1024; off <<= 1) {
        int t = (threadIdx.x >= (unsigned)off) ? sh[threadIdx.x - off] : 0;
        __syncthreads();
        sh[threadIdx.x] += t;
        __syncthreads();
    }
    int total = sh[1023];
    if (threadIdx.x == 0) {
        if (bid == 0) {
            g_prefv[0] = total;
            __threadfence();
            atomicExch(&g_state[0], 2);
            s_excl = 0;
        } else {
            g_aggv[bid] = total;
            __threadfence();
            atomicExch(&g_state[bid], 1);
            int excl = 0, j = bid - 1;
            while (j >= 0) {
                int st;
                do { st = atomicAdd(&g_state[j], 0); } while (st == 0);
                if (st == 2) { excl += atomicAdd(&g_prefv[j], 0); break; }
                excl += atomicAdd(&g_aggv[j], 0);
                j--;
            }
            g_prefv[bid] = excl + total;
            __threadfence();
            atomicExch(&g_state[bid], 2);
            s_excl = excl;
        }
    }
    __syncthreads();
    int excl = s_excl;
    if (i < NN) {
        g_rowptr[i] = sh[threadIdx.x] - v + excl;
        g_invdeg[i] = 1.0f / fmaxf((float)v, 1.0f);
    }
    if (bid == NB - 1 && threadIdx.x == 1023) g_rowptr[NN] = excl + total;
}

__global__ void fill_k(const int* __restrict__ src, const int* __restrict__ dst) {
    int i = blockIdx.x * blockDim.x + threadIdx.x;
    if (i < NE) {
        int d = dst[i];
        int pos = g_rowptr[d] + atomicAdd(&g_cursor[d], 1);
        g_csr[pos] = src[i];
    }
}

// ---------------- aggregation: one warp per node, float4 per lane ----------
__global__ void agg_k(const float* __restrict__ emb, int layer) {
    const float* __restrict__ x = (layer == 0) ? emb : g_xs[layer - 1];
    int warp = (blockIdx.x * blockDim.x + threadIdx.x) >> 5;
    int lane = threadIdx.x & 31;
    if (warp >= NN) return;
    int beg = g_rowptr[warp], end = g_rowptr[warp + 1];
    const float* xb = x + lane * 4;
    float4 acc = make_float4(0.f, 0.f, 0.f, 0.f);
    int j = beg;
    for (; j + 1 < end; j += 2) {
        int s0 = g_csr[j], s1 = g_csr[j + 1];
        float4 v0 = *(const float4*)(xb + (size_t)s0 * HH);
        float4 v1 = *(const float4*)(xb + (size_t)s1 * HH);
        acc.x += v0.x + v1.x; acc.y += v0.y + v1.y;
        acc.z += v0.z + v1.z; acc.w += v0.w + v1.w;
    }
    if (j < end) {
        int s0 = g_csr[j];
        float4 v0 = *(const float4*)(xb + (size_t)s0 * HH);
        acc.x += v0.x; acc.y += v0.y; acc.z += v0.z; acc.w += v0.w;
    }
    float inv = g_invdeg[warp];
    acc.x *= inv; acc.y *= inv; acc.z *= inv; acc.w *= inv;
    *(float4*)(g_agg + (size_t)warp * HH + lane * 4) = acc;
}

// ---------------- shared GEMM machinery -------------------------------------
// dynamic smem layout (words): buf0 {Ah,Al,Bh,Bl} buf1 {Ah,Al,Bh,Bl} then red floats
struct Frag { unsigned aH0[4], aL0[4], aH1[4], aL1[4], bh[8][2], bl[8][2]; };

__device__ __forceinline__ void mma_chunk(
    float acc[2][8][4], uint32_t sh_base, int cur, int wm, int wn, int lane) {
    int lr = lane & 7, lg8 = ((lane >> 3) & 1) * 8, lk4 = ((lane >> 4) & 1) * 4;
    uint32_t base = sh_base + (uint32_t)cur * 4 * PLANE * 4;
    uint32_t rowA = (uint32_t)(wm * 32 + lg8 + lr) * (STRD * 4);
    uint32_t rowB0 = (uint32_t)(wn * 64 + lg8 + lr) * (STRD * 4);
    #pragma unroll
    for (int s = 0; s < 2; s++) {
        uint32_t kb = (uint32_t)(s * 8 + lk4) * 4;
        Frag f;
        ldsm4(f.aH0, base + rowA + kb);
        ldsm4(f.aH1, base + rowA + 16 * (STRD * 4) + kb);
        ldsm4(f.aL0, base + PLANE * 4 + rowA + kb);
        ldsm4(f.aL1, base + PLANE * 4 + rowA + 16 * (STRD * 4) + kb);
        #pragma unroll
        for (int nt2 = 0; nt2 < 4; nt2++) {
            unsigned t[4];
            uint32_t rb = rowB0 + (uint32_t)(nt2 * 16) * (STRD * 4) + kb;
            ldsm4(t, base + 2 * PLANE * 4 + rb);
            f.bh[2*nt2][0] = t[0]; f.bh[2*nt2+1][0] = t[1];
            f.bh[2*nt2][1] = t[2]; f.bh[2*nt2+1][1] = t[3];
            ldsm4(t, base + 3 * PLANE * 4 + rb);
            f.bl[2*nt2][0] = t[0]; f.bl[2*nt2+1][0] = t[1];
            f.bl[2*nt2][1] = t[2]; f.bl[2*nt2+1][1] = t[3];
        }
        #pragma unroll
        for (int mt = 0; mt < 2; mt++) {
            const unsigned* aH = mt ? f.aH1 : f.aH0;
            const unsigned* aL = mt ? f.aL1 : f.aL0;
            #pragma unroll
            for (int nt = 0; nt < 8; nt++) {
                MMA16816(acc[mt][nt], aH, f.bh[nt]);
                MMA16816(acc[mt][nt], aH, f.bl[nt]);
                MMA16816(acc[mt][nt], aL, f.bh[nt]);
            }
        }
    }
}

// store staged A regs (16 floats) into smem hi/lo planes with cvt
__device__ __forceinline__ void storeA(unsigned* smem_u, int cur, int arow, int half,
                                       const float4 va[4]) {
    unsigned* Ah = smem_u + (size_t)cur * 4 * PLANE;
    unsigned* Al = Ah + PLANE;
    #pragma unroll
    for (int t = 0; t < 4; t++) {
        unsigned h0, l0, h1, l1;
        cvt_hilo(va[t].x, va[t].y, h0, l0);
        cvt_hilo(va[t].z, va[t].w, h1, l1);
        int j = arow * STRD + half * 8 + t * 2;
        Ah[j] = h0; Ah[j + 1] = h1;
        Al[j] = l0; Al[j + 1] = l1;
    }
}

// issue cp.async for B chunk (hi+lo planes) into buffer `buf`
__device__ __forceinline__ void loadB_async(uint32_t sh_base, int buf, int tid,
                                            const unsigned* WH, const unsigned* WL,
                                            int k0, int rowstride) {
    uint32_t bh_base = sh_base + ((uint32_t)buf * 4 * PLANE + 2 * PLANE) * 4;
    uint32_t bl_base = bh_base + PLANE * 4;
    #pragma unroll
    for (int it = 0; it < 2; it++) {
        int c = tid + it * 256;
        int row = c >> 2, part = c & 3;
        uint32_t doff = (uint32_t)(row * STRD + part * 4) * 4;
        const unsigned* sh = WH + (size_t)row * rowstride + (k0 >> 1) + part * 4;
        const unsigned* sl = WL + (size_t)row * rowstride + (k0 >> 1) + part * 4;
        CP16(bh_base + doff, sh);
        CP16(bl_base + doff, sl);
    }
}

// ---------------- fused GEMM (K=256) + bias + LN + ReLU + residual ---------
__global__ __launch_bounds__(256) void gemm_ln_k(
    const float* __restrict__ emb, int layer,
    const float* __restrict__ bl_all,
    const float* __restrict__ gamma_all, const float* __restrict__ beta_all) {
    extern __shared__ unsigned smem_u[];
    float* red = (float*)(smem_u + 8 * PLANE);   // red_s[2][128], red_q[2][128]

    const float* __restrict__ xin = (layer == 0) ? emb : g_xs[layer - 1];
    float* __restrict__ xout = g_xs[layer];
    const unsigned* WH = (const unsigned*)g_Wb[layer][0];
    const unsigned* WL = (const unsigned*)g_Wb[layer][1];
    const float* __restrict__ bias  = bl_all + layer * 128;
    const float* __restrict__ gamma = gamma_all + layer * 128;
    const float* __restrict__ beta  = beta_all + layer * 128;

    int tid = threadIdx.x, wid = tid >> 5, lane = tid & 31;
    int wm = wid & 3, wn = wid >> 2;
    int n0 = blockIdx.x * 128;
    int arow = tid >> 1, half = tid & 1;
    uint32_t sh_base = (uint32_t)__cvta_generic_to_shared(smem_u);

    float acc[2][8][4];
    #pragma unroll
    for (int mt = 0; mt < 2; mt++)
        #pragma unroll
        for (int nt = 0; nt < 8; nt++)
            #pragma unroll
            for (int c = 0; c < 4; c++) acc[mt][nt][c] = 0.f;

    float4 va[4];
    int nrow = n0 + arow;
    auto loadA = [&](int ch) {
        int k0 = ch * 32;
        const float* srcp = (k0 < HH) ? (g_agg + (size_t)nrow * HH + k0)
                                      : (xin + (size_t)nrow * HH + (k0 - HH));
        #pragma unroll
        for (int t = 0; t < 4; t++) {
            va[t] = make_float4(0.f, 0.f, 0.f, 0.f);
            if (nrow < NN) va[t] = *(const float4*)(srcp + half * 16 + t * 4);
        }
    };

    loadA(0);
    loadB_async(sh_base, 0, tid, WH, WL, 0, 128);
    CP_COMMIT();
    #pragma unroll 2
    for (int ch = 0; ch < 8; ch++) {
        int cur = ch & 1;
        storeA(smem_u, cur, arow, half, va);
        if (ch + 1 < 8) {
            loadA(ch + 1);
            loadB_async(sh_base, cur ^ 1, tid, WH, WL, (ch + 1) * 32, 128);
            CP_COMMIT();
            CP_WAIT(1);
        } else {
            CP_WAIT(0);
        }
        __syncthreads();
        mma_chunk(acc, sh_base, cur, wm, wn, lane);
    }
    __syncthreads();

    // ---- epilogue: bias -> LN -> ReLU -> residual ----
    float* red_s = red;            // [2][128]
    float* red_q = red + 256;      // [2][128]
    int cbase = wn * 64 + (lane & 3) * 2;
    float bb[8][2], gg[8][2], be[8][2];
    #pragma unroll
    for (int nt = 0; nt < 8; nt++) {
        int col = cbase + nt * 8;
        bb[nt][0] = bias[col];  bb[nt][1] = bias[col + 1];
        gg[nt][0] = gamma[col]; gg[nt][1] = gamma[col + 1];
        be[nt][0] = beta[col];  be[nt][1] = beta[col + 1];
    }
    #pragma unroll
    for (int mt = 0; mt < 2; mt++)
        #pragma unroll
        for (int rr = 0; rr < 2; rr++) {
            float s = 0.f, q2 = 0.f;
            #pragma unroll
            for (int nt = 0; nt < 8; nt++)
                #pragma unroll
                for (int q = 0; q < 2; q++) {
                    float v = acc[mt][nt][rr * 2 + q] + bb[nt][q];
                    acc[mt][nt][rr * 2 + q] = v;
                    s += v; q2 += v * v;
                }
            s  += __shfl_xor_sync(0xffffffffu, s, 1);
            s  += __shfl_xor_sync(0xffffffffu, s, 2);
            q2 += __shfl_xor_sync(0xffffffffu, q2, 1);
            q2 += __shfl_xor_sync(0xffffffffu, q2, 2);
            if ((lane & 3) == 0) {
                int rb = wm * 32 + mt * 16 + rr * 8 + (lane >> 2);
                red_s[wn * 128 + rb] = s; red_q[wn * 128 + rb] = q2;
            }
        }
    __syncthreads();
    const float inv128 = 1.0f / 128.0f;
    #pragma unroll
    for (int mt = 0; mt < 2; mt++)
        #pragma unroll
        for (int rr = 0; rr < 2; rr++) {
            int rb = wm * 32 + mt * 16 + rr * 8 + (lane >> 2);
            int n = n0 + rb;
            float S = red_s[rb] + red_s[128 + rb];
            float Q = red_q[rb] + red_q[128 + rb];
            float mu = S * inv128;
            float var = Q * inv128 - mu * mu;
            float rs = rsqrtf(var + 1e-5f);
            if (n < NN) {
                #pragma unroll
                for (int nt = 0; nt < 8; nt++) {
                    int col = cbase + nt * 8;
                    float y0 = (acc[mt][nt][rr*2+0] - mu) * rs * gg[nt][0] + be[nt][0];
                    float y1 = (acc[mt][nt][rr*2+1] - mu) * rs * gg[nt][1] + be[nt][1];
                    y0 = fmaxf(y0, 0.f); y1 = fmaxf(y1, 0.f);
                    if (layer > 0) {
                        float2 rv = *(const float2*)(xin + (size_t)n * HH + col);
                        y0 += rv.x; y1 += rv.y;
                    }
                    *(float2*)(xout + (size_t)n * HH + col) = make_float2(y0, y1);
                }
            }
        }
}

// ---------------- JK head: K=512 tensor-core GEMM + bias -------------------
__global__ __launch_bounds__(256) void jk_k(
    const float* __restrict__ emb, const float* __restrict__ jkb,
    float* __restrict__ out) {
    extern __shared__ unsigned smem_u[];
    int tid = threadIdx.x, wid = tid >> 5, lane = tid & 31;
    int wm = wid & 3, wn = wid >> 2;
    int n0 = blockIdx.x * 128;
    int arow = tid >> 1, half = tid & 1;
    uint32_t sh_base = (uint32_t)__cvta_generic_to_shared(smem_u);
    const unsigned* WH = (const unsigned*)g_jkWb[0];
    const unsigned* WL = (const unsigned*)g_jkWb[1];

    float acc[2][8][4];
    #pragma unroll
    for (int mt = 0; mt < 2; mt++)
        #pragma unroll
        for (int nt = 0; nt < 8; nt++)
            #pragma unroll
            for (int c = 0; c < 4; c++) acc[mt][nt][c] = 0.f;

    float4 va[4];
    int nrow = n0 + arow;
    auto loadA = [&](int ch) {
        const float* base = (ch < 4) ? emb : g_xs[(ch >> 2) - 1];
        const float* srcp = base + (size_t)nrow * HH + (ch & 3) * 32;
        #pragma unroll
        for (int t = 0; t < 4; t++) {
            va[t] = make_float4(0.f, 0.f, 0.f, 0.f);
            if (nrow < NN) va[t] = *(const float4*)(srcp + half * 16 + t * 4);
        }
    };

    loadA(0);
    loadB_async(sh_base, 0, tid, WH, WL, 0, 256);
    CP_COMMIT();
    #pragma unroll 2
    for (int ch = 0; ch < 16; ch++) {
        int cur = ch & 1;
        storeA(smem_u, cur, arow, half, va);
        if (ch + 1 < 16) {
            loadA(ch + 1);
            loadB_async(sh_base, cur ^ 1, tid, WH, WL, (ch + 1) * 32, 256);
            CP_COMMIT();
            CP_WAIT(1);
        } else {
            CP_WAIT(0);
        }
        __syncthreads();
        mma_chunk(acc, sh_base, cur, wm, wn, lane);
    }

    int cbase = wn * 64 + (lane & 3) * 2;
    float bb[8][2];
    #pragma unroll
    for (int nt = 0; nt < 8; nt++) {
        int col = cbase + nt * 8;
        bb[nt][0] = jkb[col]; bb[nt][1] = jkb[col + 1];
    }
    #pragma unroll
    for (int mt = 0; mt < 2; mt++)
        #pragma unroll
        for (int rr = 0; rr < 2; rr++) {
            int rb = wm * 32 + mt * 16 + rr * 8 + (lane >> 2);
            int n = n0 + rb;
            if (n < NN) {
                #pragma unroll
                for (int nt = 0; nt < 8; nt++) {
                    int col = cbase + nt * 8;
                    *(float2*)(out + (size_t)n * HH + col) =
                        make_float2(acc[mt][nt][rr*2+0] + bb[nt][0],
                                    acc[mt][nt][rr*2+1] + bb[nt][1]);
                }
            }
        }
}

// ---------------- launch ----------------------------------------------------
extern "C" void kernel_launch(void* const* d_in, const int* in_sizes, int n_in,
                              void* d_out, int out_size) {
    const float* emb   = (const float*)d_in[0];
    const float* Wl    = (const float*)d_in[1];
    const float* bl    = (const float*)d_in[2];
    const float* Wr    = (const float*)d_in[3];
    const float* gamma = (const float*)d_in[4];
    const float* beta  = (const float*)d_in[5];
    const float* jkW   = (const float*)d_in[6];
    const float* jkb   = (const float*)d_in[7];
    const int*   eidx  = (const int*)d_in[8];
    const int* src = eidx;
    const int* dst = eidx + NE;
    float* out = (float*)d_out;

    const int SMEMSZ = 8 * PLANE * 4 + 4 * 512;   // 81920 + 2048 = 83968 B
    static bool attr_set = false;
    if (!attr_set) {
        cudaFuncSetAttribute(gemm_ln_k, cudaFuncAttributeMaxDynamicSharedMemorySize, SMEMSZ);
        cudaFuncSetAttribute(jk_k,      cudaFuncAttributeMaxDynamicSharedMemorySize, SMEMSZ);
        attr_set = true;
    }

    const int initN = NL * 128 * 256 + 128 * 512;   // 163840 > NN
    init_k<<<(initN + 255) / 256, 256>>>(Wl, Wr, jkW);
    count_k<<<(NE + 255) / 256, 256>>>(dst);
    scan_k<<<NB, 1024>>>();
    fill_k<<<(NE + 255) / 256, 256>>>(src, dst);

    const int GB = (NN + 127) / 128;   // 782
    for (int l = 0; l < NL; l++) {
        agg_k<<<(NN + 7) / 8, 256>>>(emb, l);
        gemm_ln_k<<<GB, 256, SMEMSZ>>>(emb, l, bl, gamma, beta);
    }
    jk_k<<<GB, 256, SMEMSZ>>>(emb, jkb, out);
}